// round 2
// baseline (speedup 1.0000x reference)
#include <cuda_runtime.h>
#include <math.h>

#define EDIM 1024
#define NH   16
#define HD   64
#define BB   2
#define SS   2048
#define MTOT (BB*SS)   // 4096

typedef unsigned long long ull;

__device__ __forceinline__ ull fma2(ull a, ull b, ull c) {
    ull d; asm("fma.rn.f32x2 %0,%1,%2,%3;" : "=l"(d) : "l"(a), "l"(b), "l"(c)); return d;
}
__device__ __forceinline__ ull mul2(ull a, ull b) {
    ull d; asm("mul.rn.f32x2 %0,%1,%2;" : "=l"(d) : "l"(a), "l"(b)); return d;
}
__device__ __forceinline__ ull add2(ull a, ull b) {
    ull d; asm("add.rn.f32x2 %0,%1,%2;" : "=l"(d) : "l"(a), "l"(b)); return d;
}
__device__ __forceinline__ ull pack2(float x, float y) {
    ull d; asm("mov.b64 %0,{%1,%2};" : "=l"(d) : "f"(x), "f"(y)); return d;
}
__device__ __forceinline__ float2 unpack2(ull a) {
    float2 r; asm("mov.b64 {%0,%1},%2;" : "=f"(r.x), "=f"(r.y) : "l"(a)); return r;
}

// Scratch (static device globals — no allocation in kernel_launch)
__device__ float g_Q[MTOT*EDIM];
__device__ float g_K[MTOT*EDIM];
__device__ float g_V[MTOT*EDIM];
__device__ float g_ctx[MTOT*EDIM];

// ---------------------------------------------------------------------------
// GEMM (f32x2): C[M,N] = A[M,K] @ W[K,N] + bias.  M=4096, N=K=1024.
// 128x64 tile, BK=16, 256 threads. Micro-tile 8(M)x4(N) per thread as
// 4 m-pairs x 4 n of f32x2. B stored duplicated (b,b) in SMEM -> zero packs.
// ---------------------------------------------------------------------------
#define BM 128
#define BN 64
#define BK 16
#define ASTR 136   // floats per As row (conflict-free for transposed stores)
#define BSTR 136   // floats per Bs row (128 used)

__global__ __launch_bounds__(256)
void gemm_bias(const float* __restrict__ A, const float* __restrict__ W,
               const float* __restrict__ bias, float* __restrict__ C,
               int head_layout)
{
    __shared__ float As[BK * ASTR];   // [k][m] transposed
    __shared__ float Bs[BK * BSTR];   // [k][2*n] duplicated pairs

    const int tid = threadIdx.x;
    const int tx = tid & 15;          // n direction: 16 groups x 4 n
    const int ty = tid >> 4;          // m direction: 16 groups x 8 m
    const int m0 = blockIdx.x * BM;
    const int n0 = blockIdx.y * BN;

    ull acc[4][4];
#pragma unroll
    for (int i = 0; i < 4; i++)
#pragma unroll
        for (int j = 0; j < 4; j++) acc[i][j] = 0ull;

    // global load indices
    const int ar0 = tid >> 2;              // A row for load 0 (0..63)
    const int akc = (tid & 3) * 4;         // A k col
    const int bkr = tid >> 4;              // W k row
    const int bnc = (tid & 15) * 4;        // W n col

    for (int k0 = 0; k0 < EDIM; k0 += BK) {
        // A tile: 128 rows x 16 k -> transposed into As[k][m]
#pragma unroll
        for (int i = 0; i < 2; i++) {
            int r = ar0 + i * 64;
            float4 a = *reinterpret_cast<const float4*>(&A[(size_t)(m0 + r) * EDIM + k0 + akc]);
            As[(akc + 0) * ASTR + r] = a.x;
            As[(akc + 1) * ASTR + r] = a.y;
            As[(akc + 2) * ASTR + r] = a.z;
            As[(akc + 3) * ASTR + r] = a.w;
        }
        // W tile: 16 k x 64 n -> duplicated pairs
        {
            float4 b = *reinterpret_cast<const float4*>(&W[(size_t)(k0 + bkr) * EDIM + n0 + bnc]);
            float4 d0 = make_float4(b.x, b.x, b.y, b.y);
            float4 d1 = make_float4(b.z, b.z, b.w, b.w);
            *reinterpret_cast<float4*>(&Bs[bkr * BSTR + bnc * 2]) = d0;
            *reinterpret_cast<float4*>(&Bs[bkr * BSTR + bnc * 2 + 4]) = d1;
        }
        __syncthreads();

#pragma unroll
        for (int k = 0; k < BK; k++) {
            const ull* ap = reinterpret_cast<const ull*>(&As[k * ASTR + ty * 8]);
            const ull* bp = reinterpret_cast<const ull*>(&Bs[k * BSTR + tx * 8]);
            ull a0 = ap[0], a1 = ap[1], a2 = ap[2], a3 = ap[3];
            ull b0 = bp[0], b1 = bp[1], b2 = bp[2], b3 = bp[3];
            acc[0][0] = fma2(a0, b0, acc[0][0]);
            acc[0][1] = fma2(a0, b1, acc[0][1]);
            acc[0][2] = fma2(a0, b2, acc[0][2]);
            acc[0][3] = fma2(a0, b3, acc[0][3]);
            acc[1][0] = fma2(a1, b0, acc[1][0]);
            acc[1][1] = fma2(a1, b1, acc[1][1]);
            acc[1][2] = fma2(a1, b2, acc[1][2]);
            acc[1][3] = fma2(a1, b3, acc[1][3]);
            acc[2][0] = fma2(a2, b0, acc[2][0]);
            acc[2][1] = fma2(a2, b1, acc[2][1]);
            acc[2][2] = fma2(a2, b2, acc[2][2]);
            acc[2][3] = fma2(a2, b3, acc[2][3]);
            acc[3][0] = fma2(a3, b0, acc[3][0]);
            acc[3][1] = fma2(a3, b1, acc[3][1]);
            acc[3][2] = fma2(a3, b2, acc[3][2]);
            acc[3][3] = fma2(a3, b3, acc[3][3]);
        }
        __syncthreads();
    }

    const int n = n0 + tx * 4;
    float4 bv = *reinterpret_cast<const float4*>(&bias[n]);

#pragma unroll
    for (int i = 0; i < 4; i++) {
        float2 c0 = unpack2(acc[i][0]);
        float2 c1 = unpack2(acc[i][1]);
        float2 c2 = unpack2(acc[i][2]);
        float2 c3 = unpack2(acc[i][3]);
        float4 rlo = make_float4(c0.x + bv.x, c1.x + bv.y, c2.x + bv.z, c3.x + bv.w);
        float4 rhi = make_float4(c0.y + bv.x, c1.y + bv.y, c2.y + bv.z, c3.y + bv.w);
        int mlo = m0 + ty * 8 + 2 * i;
#pragma unroll
        for (int h2 = 0; h2 < 2; h2++) {
            int m = mlo + h2;
            float4 r = h2 ? rhi : rlo;
            if (head_layout) {
                int b_ = m >> 11;
                int s_ = m & (SS - 1);
                int h  = n >> 6;
                int d  = n & (HD - 1);
                float* dst = g_Q; // placeholder, overwritten below
                dst = C + (((size_t)(b_ * NH + h) * SS + s_) * HD + d);
                *reinterpret_cast<float4*>(dst) = r;
            } else {
                *reinterpret_cast<float4*>(&C[(size_t)m * EDIM + n]) = r;
            }
        }
    }
}

// ---------------------------------------------------------------------------
// Flash-style attention (f32x2): 1 query row per thread, online softmax.
// grid = (S/128, B*H), block = 128.
// ---------------------------------------------------------------------------
__global__ __launch_bounds__(128)
void attn_kernel(const float* __restrict__ mask)
{
    const int bh = blockIdx.y;
    const int b_ = bh >> 4;
    const int h  = bh & (NH - 1);
    const int qi = blockIdx.x * 128 + threadIdx.x;

    __shared__ float Ks[32 * HD];
    __shared__ float Vs[32 * HD];
    __shared__ float madd[32];

    // q row: 32 f32x2 pairs
    ull q2[32];
    {
        const ull* Qp = reinterpret_cast<const ull*>(g_Q + ((size_t)bh * SS + qi) * HD);
#pragma unroll
        for (int i = 0; i < 32; i++) q2[i] = Qp[i];
    }

    ull acc2[32];
#pragma unroll
    for (int i = 0; i < 32; i++) acc2[i] = 0ull;
    float mval = -1e30f;
    float l = 0.f;

    const float scale = 0.125f;  // 1/sqrt(64)

    for (int k0 = 0; k0 < SS; k0 += 32) {
        const float4* Kp = reinterpret_cast<const float4*>(g_K + ((size_t)bh * SS + k0) * HD);
        const float4* Vp = reinterpret_cast<const float4*>(g_V + ((size_t)bh * SS + k0) * HD);
        float4* Ks4 = reinterpret_cast<float4*>(Ks);
        float4* Vs4 = reinterpret_cast<float4*>(Vs);
#pragma unroll
        for (int i = 0; i < 4; i++) {
            Ks4[i * 128 + threadIdx.x] = Kp[i * 128 + threadIdx.x];
            Vs4[i * 128 + threadIdx.x] = Vp[i * 128 + threadIdx.x];
        }
        if (threadIdx.x < 32)
            madd[threadIdx.x] = (1.0f - mask[b_ * SS + k0 + threadIdx.x]) * -10000.0f;
        __syncthreads();

        const ull* Kt = reinterpret_cast<const ull*>(Ks);
        const ull* Vt = reinterpret_cast<const ull*>(Vs);

#pragma unroll 2
        for (int j = 0; j < 32; j++) {
            const ull* kr = Kt + j * 32;
            // 4 parallel f32x2 accumulators to break the dependency chain
            ull s0 = 0ull, s1 = 0ull, s2 = 0ull, s3 = 0ull;
#pragma unroll
            for (int i = 0; i < 8; i++) {
                s0 = fma2(q2[i * 4 + 0], kr[i * 4 + 0], s0);
                s1 = fma2(q2[i * 4 + 1], kr[i * 4 + 1], s1);
                s2 = fma2(q2[i * 4 + 2], kr[i * 4 + 2], s2);
                s3 = fma2(q2[i * 4 + 3], kr[i * 4 + 3], s3);
            }
            s0 = add2(s0, s1);
            s2 = add2(s2, s3);
            s0 = add2(s0, s2);
            float2 sp = unpack2(s0);
            float s = (sp.x + sp.y) * scale + madd[j];

            float mn = fmaxf(mval, s);
            float p;
            if (mn > mval) {
                float corr = __expf(mval - mn);
                l *= corr;
                ull c2 = pack2(corr, corr);
#pragma unroll
                for (int d = 0; d < 32; d++) acc2[d] = mul2(acc2[d], c2);
                mval = mn;
                p = 1.0f;
            } else {
                p = __expf(s - mval);
            }
            l += p;
            ull pk = pack2(p, p);
            const ull* vr = Vt + j * 32;
#pragma unroll
            for (int d = 0; d < 32; d++) acc2[d] = fma2(pk, vr[d], acc2[d]);
        }
        __syncthreads();
    }

    float inv = 1.0f / l;
    ull inv2 = pack2(inv, inv);
    float* Cp = g_ctx + ((size_t)(b_ * SS + qi) * EDIM) + h * HD;
#pragma unroll
    for (int i = 0; i < 16; i++) {
        ull r0 = mul2(acc2[i * 2 + 0], inv2);
        ull r1 = mul2(acc2[i * 2 + 1], inv2);
        float2 f0 = unpack2(r0);
        float2 f1 = unpack2(r1);
        *reinterpret_cast<float4*>(&Cp[i * 4]) = make_float4(f0.x, f0.y, f1.x, f1.y);
    }
}

// ---------------------------------------------------------------------------
extern "C" void kernel_launch(void* const* d_in, const int* in_sizes, int n_in,
                              void* d_out, int out_size)
{
    const float* X    = (const float*)d_in[0];
    const float* mask = (const float*)d_in[1];
    const float* Wq   = (const float*)d_in[2];
    const float* bq   = (const float*)d_in[3];
    const float* Wk   = (const float*)d_in[4];
    const float* bk   = (const float*)d_in[5];
    const float* Wv   = (const float*)d_in[6];
    const float* bv   = (const float*)d_in[7];
    const float* Wo   = (const float*)d_in[8];
    const float* bo   = (const float*)d_in[9];
    float* out = (float*)d_out;

    float *Qd, *Kd, *Vd, *Cd;
    cudaGetSymbolAddress((void**)&Qd, g_Q);
    cudaGetSymbolAddress((void**)&Kd, g_K);
    cudaGetSymbolAddress((void**)&Vd, g_V);
    cudaGetSymbolAddress((void**)&Cd, g_ctx);

    dim3 ggrid(MTOT / BM, EDIM / BN);
    gemm_bias<<<ggrid, 256>>>(X, Wq, bq, Qd, 1);
    gemm_bias<<<ggrid, 256>>>(X, Wk, bk, Kd, 1);
    gemm_bias<<<ggrid, 256>>>(X, Wv, bv, Vd, 1);

    dim3 agrid(SS / 128, BB * NH);
    attn_kernel<<<agrid, 128>>>(mask);

    gemm_bias<<<ggrid, 256>>>(Cd, Wo, bo, out, 0);
}

// round 5
// speedup vs baseline: 1.6388x; 1.6388x over previous
#include <cuda_runtime.h>
#include <math.h>
#include <cstdint>

#define EDIM 1024
#define NH   16
#define HD   64
#define BB   2
#define SS   2048
#define MTOT (BB*SS)   // 4096

// Scratch
__device__ float g_Q[MTOT*EDIM];
__device__ float g_K[MTOT*EDIM];
__device__ float g_V[MTOT*EDIM];
__device__ float g_ctx[MTOT*EDIM];
__device__ float g_Wt[4][EDIM*EDIM];   // transposed weights [n][k]

__device__ __forceinline__ uint32_t cvt_tf32(float x) {
    uint32_t r; asm("cvt.rna.tf32.f32 %0, %1;" : "=r"(r) : "f"(x));
    return r;
}

// ============================ transpose 1024x1024 ============================
__global__ __launch_bounds__(256)
void transpose1024(const float* __restrict__ in, float* __restrict__ out)
{
    __shared__ float t[32][33];
    int x = blockIdx.x * 32 + threadIdx.x;
    int y = blockIdx.y * 32 + threadIdx.y;
#pragma unroll
    for (int j = 0; j < 32; j += 8)
        t[threadIdx.y + j][threadIdx.x] = in[(size_t)(y + j) * EDIM + x];
    __syncthreads();
    x = blockIdx.y * 32 + threadIdx.x;
    y = blockIdx.x * 32 + threadIdx.y;
#pragma unroll
    for (int j = 0; j < 32; j += 8)
        out[(size_t)(y + j) * EDIM + x] = t[threadIdx.x][threadIdx.y + j];
}

// ============================ tf32 mma.sync GEMM ============================
// C[M,N] = A[M,K] @ W[K,N] + bias, Wt = W^T ([N][K] row-major).
// Block tile 128x128, BK=32, 8 warps (4m x 2n), warp tile 32x64.
#define GBM 128
#define GBN 128
#define GBK 32
#define LDP 36
#define TILE_U32 (128 * LDP)

__device__ __forceinline__ void mma_tf32(float& d0, float& d1, float& d2, float& d3,
                                         uint32_t a0, uint32_t a1, uint32_t a2, uint32_t a3,
                                         uint32_t b0, uint32_t b1) {
    asm volatile(
        "mma.sync.aligned.m16n8k8.row.col.f32.tf32.tf32.f32 "
        "{%0,%1,%2,%3},{%4,%5,%6,%7},{%8,%9},{%0,%1,%2,%3};"
        : "+f"(d0), "+f"(d1), "+f"(d2), "+f"(d3)
        : "r"(a0), "r"(a1), "r"(a2), "r"(a3), "r"(b0), "r"(b1));
}

__global__ __launch_bounds__(256)
void gemm_mma(const float* __restrict__ A, const float* __restrict__ Wt,
              const float* __restrict__ bias, float* __restrict__ C, int head_layout)
{
    extern __shared__ uint32_t sm[];
    uint32_t* As[2] = { sm,                sm + 2 * TILE_U32 };
    uint32_t* Bs[2] = { sm + TILE_U32,     sm + 3 * TILE_U32 };

    const int tid = threadIdx.x;
    const int wid = tid >> 5;
    const int lane = tid & 31;
    const int m0 = blockIdx.x * GBM;
    const int n0 = blockIdx.y * GBN;
    const int warp_m = (wid & 3) * 32;
    const int warp_n = (wid >> 2) * 64;
    const int r4 = lane >> 2;
    const int c4 = lane & 3;

    float acc[2][8][4];
#pragma unroll
    for (int mt = 0; mt < 2; mt++)
#pragma unroll
        for (int nt = 0; nt < 8; nt++)
#pragma unroll
            for (int i = 0; i < 4; i++) acc[mt][nt][i] = 0.f;

    // staging: 256 threads, each covers 16 floats (4 float4) per operand tile
    const int sr = tid >> 1;              // row 0..127
    const int sc = (tid & 1) * 16;        // col base: 0 or 16
    auto stage = [&](int buf, int k0) {
        uint32_t* Ad = As[buf];
        uint32_t* Bd = Bs[buf];
#pragma unroll
        for (int i = 0; i < 4; i++) {
            float4 v = *reinterpret_cast<const float4*>(&A[(size_t)(m0 + sr) * EDIM + k0 + sc + i * 4]);
            uint32_t* p = &Ad[sr * LDP + sc + i * 4];
            p[0] = cvt_tf32(v.x); p[1] = cvt_tf32(v.y); p[2] = cvt_tf32(v.z); p[3] = cvt_tf32(v.w);
        }
#pragma unroll
        for (int i = 0; i < 4; i++) {
            float4 v = *reinterpret_cast<const float4*>(&Wt[(size_t)(n0 + sr) * EDIM + k0 + sc + i * 4]);
            uint32_t* p = &Bd[sr * LDP + sc + i * 4];
            p[0] = cvt_tf32(v.x); p[1] = cvt_tf32(v.y); p[2] = cvt_tf32(v.z); p[3] = cvt_tf32(v.w);
        }
    };

    stage(0, 0);
    __syncthreads();

    const int NCHUNK = EDIM / GBK;   // 32
    for (int c = 0; c < NCHUNK; c++) {
        const int cur = c & 1;
        if (c + 1 < NCHUNK) stage(cur ^ 1, (c + 1) * GBK);

        const uint32_t* Ab = As[cur];
        const uint32_t* Bb = Bs[cur];
#pragma unroll
        for (int ks = 0; ks < 4; ks++) {
            const int kb = ks * 8;
            uint32_t af[2][4];
#pragma unroll
            for (int mt = 0; mt < 2; mt++) {
                const uint32_t* base = &Ab[(warp_m + mt * 16 + r4) * LDP + kb + c4];
                af[mt][0] = base[0];
                af[mt][1] = base[8 * LDP];
                af[mt][2] = base[4];
                af[mt][3] = base[8 * LDP + 4];
            }
            uint32_t bf[8][2];
#pragma unroll
            for (int nt = 0; nt < 8; nt++) {
                const uint32_t* base = &Bb[(warp_n + nt * 8 + r4) * LDP + kb + c4];
                bf[nt][0] = base[0];
                bf[nt][1] = base[4];
            }
#pragma unroll
            for (int mt = 0; mt < 2; mt++)
#pragma unroll
                for (int nt = 0; nt < 8; nt++)
                    mma_tf32(acc[mt][nt][0], acc[mt][nt][1], acc[mt][nt][2], acc[mt][nt][3],
                             af[mt][0], af[mt][1], af[mt][2], af[mt][3],
                             bf[nt][0], bf[nt][1]);
        }
        __syncthreads();
    }

    // ---- epilogue ----
#pragma unroll
    for (int mt = 0; mt < 2; mt++) {
#pragma unroll
        for (int half = 0; half < 2; half++) {
            const int m = m0 + warp_m + mt * 16 + r4 + half * 8;
            const int b_ = m >> 11;
            const int s_ = m & (SS - 1);
#pragma unroll
            for (int nt = 0; nt < 8; nt++) {
                const int col = n0 + warp_n + nt * 8 + 2 * c4;
                float2 o;
                o.x = acc[mt][nt][half * 2 + 0] + bias[col];
                o.y = acc[mt][nt][half * 2 + 1] + bias[col + 1];
                if (head_layout) {
                    const int h = col >> 6;
                    const int d = col & (HD - 1);
                    *reinterpret_cast<float2*>(
                        &C[(((size_t)(b_ * NH + h) * SS + s_) * HD) + d]) = o;
                } else {
                    *reinterpret_cast<float2*>(&C[(size_t)m * EDIM + col]) = o;
                }
            }
        }
    }
}

// ============================ attention (R1, unchanged) ============================
__global__ __launch_bounds__(128)
void attn_kernel(const float* __restrict__ mask)
{
    const int bh = blockIdx.y;
    const int b_ = bh >> 4;
    const int h  = bh & (NH - 1);
    const int qi = blockIdx.x * 128 + threadIdx.x;

    __shared__ float Ks[32 * HD];
    __shared__ float Vs[32 * HD];
    __shared__ float madd[32];

    float q[HD];
    {
        const float* Qp = g_Q + ((size_t)bh * SS + qi) * HD;
#pragma unroll
        for (int i = 0; i < 16; i++) {
            float4 t = *reinterpret_cast<const float4*>(&Qp[i * 4]);
            q[i * 4 + 0] = t.x; q[i * 4 + 1] = t.y; q[i * 4 + 2] = t.z; q[i * 4 + 3] = t.w;
        }
    }

    float acc[HD];
#pragma unroll
    for (int d = 0; d < HD; d++) acc[d] = 0.f;
    float mval = -1e30f;
    float l = 0.f;
    const float scale = 0.125f;

    for (int k0 = 0; k0 < SS; k0 += 32) {
        const float4* Kp = reinterpret_cast<const float4*>(g_K + ((size_t)bh * SS + k0) * HD);
        const float4* Vp = reinterpret_cast<const float4*>(g_V + ((size_t)bh * SS + k0) * HD);
        float4* Ks4 = reinterpret_cast<float4*>(Ks);
        float4* Vs4 = reinterpret_cast<float4*>(Vs);
#pragma unroll
        for (int i = 0; i < 4; i++) {
            Ks4[i * 128 + threadIdx.x] = Kp[i * 128 + threadIdx.x];
            Vs4[i * 128 + threadIdx.x] = Vp[i * 128 + threadIdx.x];
        }
        if (threadIdx.x < 32)
            madd[threadIdx.x] = (1.0f - mask[b_ * SS + k0 + threadIdx.x]) * -10000.0f;
        __syncthreads();

        const float4* Kt = reinterpret_cast<const float4*>(Ks);
        const float4* Vt = reinterpret_cast<const float4*>(Vs);

#pragma unroll 4
        for (int j = 0; j < 32; j++) {
            float s = 0.f;
#pragma unroll
            for (int d4 = 0; d4 < 16; d4++) {
                float4 kk = Kt[j * 16 + d4];
                s += q[d4 * 4 + 0] * kk.x;
                s += q[d4 * 4 + 1] * kk.y;
                s += q[d4 * 4 + 2] * kk.z;
                s += q[d4 * 4 + 3] * kk.w;
            }
            s = s * scale + madd[j];

            float mn = fmaxf(mval, s);
            float p;
            if (mn > mval) {
                float corr = __expf(mval - mn);
                l *= corr;
#pragma unroll
                for (int d = 0; d < HD; d++) acc[d] *= corr;
                mval = mn;
                p = 1.0f;
            } else {
                p = __expf(s - mval);
            }
            l += p;
#pragma unroll
            for (int d4 = 0; d4 < 16; d4++) {
                float4 vv = Vt[j * 16 + d4];
                acc[d4 * 4 + 0] += p * vv.x;
                acc[d4 * 4 + 1] += p * vv.y;
                acc[d4 * 4 + 2] += p * vv.z;
                acc[d4 * 4 + 3] += p * vv.w;
            }
        }
        __syncthreads();
    }

    float inv = 1.0f / l;
    float* Cp = g_ctx + ((size_t)(b_ * SS + qi) * EDIM) + h * HD;
#pragma unroll
    for (int d4 = 0; d4 < 16; d4++) {
        float4 r;
        r.x = acc[d4 * 4 + 0] * inv;
        r.y = acc[d4 * 4 + 1] * inv;
        r.z = acc[d4 * 4 + 2] * inv;
        r.w = acc[d4 * 4 + 3] * inv;
        *reinterpret_cast<float4*>(&Cp[d4 * 4]) = r;
    }
}

// ============================ launch ============================
extern "C" void kernel_launch(void* const* d_in, const int* in_sizes, int n_in,
                              void* d_out, int out_size)
{
    const float* X    = (const float*)d_in[0];
    const float* mask = (const float*)d_in[1];
    const float* Wq   = (const float*)d_in[2];
    const float* bq   = (const float*)d_in[3];
    const float* Wk   = (const float*)d_in[4];
    const float* bk   = (const float*)d_in[5];
    const float* Wv   = (const float*)d_in[6];
    const float* bv   = (const float*)d_in[7];
    const float* Wo   = (const float*)d_in[8];
    const float* bo   = (const float*)d_in[9];
    float* out = (float*)d_out;

    float *Qd, *Kd, *Vd, *Cd, *Wtd;
    cudaGetSymbolAddress((void**)&Qd, g_Q);
    cudaGetSymbolAddress((void**)&Kd, g_K);
    cudaGetSymbolAddress((void**)&Vd, g_V);
    cudaGetSymbolAddress((void**)&Cd, g_ctx);
    cudaGetSymbolAddress((void**)&Wtd, g_Wt);
    float* Wt0 = Wtd;
    float* Wt1 = Wtd + (size_t)EDIM * EDIM;
    float* Wt2 = Wtd + 2 * (size_t)EDIM * EDIM;
    float* Wt3 = Wtd + 3 * (size_t)EDIM * EDIM;

    const int smem_bytes = 4 * TILE_U32 * 4;   // 73728
    cudaFuncSetAttribute(gemm_mma, cudaFuncAttributeMaxDynamicSharedMemorySize, smem_bytes);

    dim3 tgrid(32, 32), tblk(32, 8);
    transpose1024<<<tgrid, tblk>>>(Wq, Wt0);
    transpose1024<<<tgrid, tblk>>>(Wk, Wt1);
    transpose1024<<<tgrid, tblk>>>(Wv, Wt2);
    transpose1024<<<tgrid, tblk>>>(Wo, Wt3);

    dim3 ggrid(MTOT / GBM, EDIM / GBN);   // 32 x 8
    gemm_mma<<<ggrid, 256, smem_bytes>>>(X, Wt0, bq, Qd, 1);
    gemm_mma<<<ggrid, 256, smem_bytes>>>(X, Wt1, bk, Kd, 1);
    gemm_mma<<<ggrid, 256, smem_bytes>>>(X, Wt2, bv, Vd, 1);

    dim3 agrid(SS / 128, BB * NH);
    attn_kernel<<<agrid, 128>>>(mask);

    gemm_mma<<<ggrid, 256, smem_bytes>>>(Cd, Wt3, bo, out, 0);
}

// round 6
// speedup vs baseline: 3.4555x; 2.1086x over previous
#include <cuda_runtime.h>
#include <math.h>
#include <cstdint>

#define EDIM 1024
#define NH   16
#define HD   64
#define BB   2
#define SS   2048
#define MTOT (BB*SS)   // 4096

// Scratch
__device__ float g_Q[MTOT*EDIM];
__device__ float g_K[MTOT*EDIM];
__device__ float g_V[MTOT*EDIM];
__device__ float g_ctx[MTOT*EDIM];
__device__ float g_Wt[4][EDIM*EDIM];   // transposed weights [n][k]

__device__ __forceinline__ uint32_t cvt_tf32(float x) {
    uint32_t r; asm("cvt.rna.tf32.f32 %0, %1;" : "=r"(r) : "f"(x));
    return r;
}

__device__ __forceinline__ void mma_tf32(float& d0, float& d1, float& d2, float& d3,
                                         uint32_t a0, uint32_t a1, uint32_t a2, uint32_t a3,
                                         uint32_t b0, uint32_t b1) {
    asm volatile(
        "mma.sync.aligned.m16n8k8.row.col.f32.tf32.tf32.f32 "
        "{%0,%1,%2,%3},{%4,%5,%6,%7},{%8,%9},{%0,%1,%2,%3};"
        : "+f"(d0), "+f"(d1), "+f"(d2), "+f"(d3)
        : "r"(a0), "r"(a1), "r"(a2), "r"(a3), "r"(b0), "r"(b1));
}

// ============================ fused transpose (grid.z selects W) ============================
__global__ __launch_bounds__(256)
void transpose4(const float* __restrict__ w0, const float* __restrict__ w1,
                const float* __restrict__ w2, const float* __restrict__ w3)
{
    const float* in = (blockIdx.z == 0) ? w0 : (blockIdx.z == 1) ? w1 : (blockIdx.z == 2) ? w2 : w3;
    float* out = g_Wt[blockIdx.z];
    __shared__ float t[32][33];
    int x = blockIdx.x * 32 + threadIdx.x;
    int y = blockIdx.y * 32 + threadIdx.y;
#pragma unroll
    for (int j = 0; j < 32; j += 8)
        t[threadIdx.y + j][threadIdx.x] = in[(size_t)(y + j) * EDIM + x];
    __syncthreads();
    x = blockIdx.y * 32 + threadIdx.x;
    y = blockIdx.x * 32 + threadIdx.y;
#pragma unroll
    for (int j = 0; j < 32; j += 8)
        out[(size_t)(y + j) * EDIM + x] = t[threadIdx.x][threadIdx.y + j];
}

// ============================ tf32 mma.sync GEMM ============================
#define GBM 128
#define GBN 128
#define GBK 32
#define LDP 36
#define TILE_U32 (128 * LDP)

struct GemmSmem { uint32_t a[2][TILE_U32]; uint32_t b[2][TILE_U32]; };

__device__ __forceinline__ void gemm_body(const float* __restrict__ A, const float* __restrict__ Wt,
                                          const float* __restrict__ bias, float* __restrict__ C,
                                          int head_layout, uint32_t* sm, int m0, int n0)
{
    uint32_t* As[2] = { sm,                sm + 2 * TILE_U32 };
    uint32_t* Bs[2] = { sm + TILE_U32,     sm + 3 * TILE_U32 };

    const int tid = threadIdx.x;
    const int wid = tid >> 5;
    const int lane = tid & 31;
    const int warp_m = (wid & 3) * 32;
    const int warp_n = (wid >> 2) * 64;
    const int r4 = lane >> 2;
    const int c4 = lane & 3;

    float acc[2][8][4];
#pragma unroll
    for (int mt = 0; mt < 2; mt++)
#pragma unroll
        for (int nt = 0; nt < 8; nt++)
#pragma unroll
            for (int i = 0; i < 4; i++) acc[mt][nt][i] = 0.f;

    const int sr = tid >> 1;
    const int sc = (tid & 1) * 16;
    auto stage = [&](int buf, int k0) {
        uint32_t* Ad = As[buf];
        uint32_t* Bd = Bs[buf];
#pragma unroll
        for (int i = 0; i < 4; i++) {
            float4 v = *reinterpret_cast<const float4*>(&A[(size_t)(m0 + sr) * EDIM + k0 + sc + i * 4]);
            uint32_t* p = &Ad[sr * LDP + sc + i * 4];
            p[0] = cvt_tf32(v.x); p[1] = cvt_tf32(v.y); p[2] = cvt_tf32(v.z); p[3] = cvt_tf32(v.w);
        }
#pragma unroll
        for (int i = 0; i < 4; i++) {
            float4 v = *reinterpret_cast<const float4*>(&Wt[(size_t)(n0 + sr) * EDIM + k0 + sc + i * 4]);
            uint32_t* p = &Bd[sr * LDP + sc + i * 4];
            p[0] = cvt_tf32(v.x); p[1] = cvt_tf32(v.y); p[2] = cvt_tf32(v.z); p[3] = cvt_tf32(v.w);
        }
    };

    stage(0, 0);
    __syncthreads();

    const int NCHUNK = EDIM / GBK;
    for (int c = 0; c < NCHUNK; c++) {
        const int cur = c & 1;
        if (c + 1 < NCHUNK) stage(cur ^ 1, (c + 1) * GBK);

        const uint32_t* Ab = As[cur];
        const uint32_t* Bb = Bs[cur];
#pragma unroll
        for (int ks = 0; ks < 4; ks++) {
            const int kb = ks * 8;
            uint32_t af[2][4];
#pragma unroll
            for (int mt = 0; mt < 2; mt++) {
                const uint32_t* base = &Ab[(warp_m + mt * 16 + r4) * LDP + kb + c4];
                af[mt][0] = base[0];
                af[mt][1] = base[8 * LDP];
                af[mt][2] = base[4];
                af[mt][3] = base[8 * LDP + 4];
            }
            uint32_t bf[8][2];
#pragma unroll
            for (int nt = 0; nt < 8; nt++) {
                const uint32_t* base = &Bb[(warp_n + nt * 8 + r4) * LDP + kb + c4];
                bf[nt][0] = base[0];
                bf[nt][1] = base[4];
            }
#pragma unroll
            for (int mt = 0; mt < 2; mt++)
#pragma unroll
                for (int nt = 0; nt < 8; nt++)
                    mma_tf32(acc[mt][nt][0], acc[mt][nt][1], acc[mt][nt][2], acc[mt][nt][3],
                             af[mt][0], af[mt][1], af[mt][2], af[mt][3],
                             bf[nt][0], bf[nt][1]);
        }
        __syncthreads();
    }

#pragma unroll
    for (int mt = 0; mt < 2; mt++) {
#pragma unroll
        for (int half = 0; half < 2; half++) {
            const int m = m0 + warp_m + mt * 16 + r4 + half * 8;
            const int b_ = m >> 11;
            const int s_ = m & (SS - 1);
#pragma unroll
            for (int nt = 0; nt < 8; nt++) {
                const int col = n0 + warp_n + nt * 8 + 2 * c4;
                float2 o;
                o.x = acc[mt][nt][half * 2 + 0] + bias[col];
                o.y = acc[mt][nt][half * 2 + 1] + bias[col + 1];
                if (head_layout) {
                    const int h = col >> 6;
                    const int d = col & (HD - 1);
                    *reinterpret_cast<float2*>(
                        &C[(((size_t)(b_ * NH + h) * SS + s_) * HD) + d]) = o;
                } else {
                    *reinterpret_cast<float2*>(&C[(size_t)m * EDIM + col]) = o;
                }
            }
        }
    }
}

// fused QKV projection: grid.z in {0,1,2} picks weight/bias/output
__global__ __launch_bounds__(256)
void gemm_qkv(const float* __restrict__ X,
              const float* __restrict__ bq, const float* __restrict__ bk,
              const float* __restrict__ bv)
{
    extern __shared__ uint32_t sm[];
    const int z = blockIdx.z;
    const float* Wt = g_Wt[z];
    const float* bias = (z == 0) ? bq : (z == 1) ? bk : bv;
    float* C = (z == 0) ? g_Q : (z == 1) ? g_K : g_V;
    gemm_body(X, Wt, bias, C, 1, sm, blockIdx.x * GBM, blockIdx.y * GBN);
}

__global__ __launch_bounds__(256)
void gemm_out(const float* __restrict__ bo, float* __restrict__ C)
{
    extern __shared__ uint32_t sm[];
    gemm_body(g_ctx, g_Wt[3], bo, C, 0, sm, blockIdx.x * GBM, blockIdx.y * GBN);
}

// ============================ flash attention with mma.sync tf32 ============================
// CTA: 128 q rows of one (b,h); 8 warps x 16 rows. KV tiles of 64.
#define LKK 68
#define LVV 72
#define LPP 68
#define AOFF_V  (64 * LKK)                 // 4352
#define AOFF_P  (AOFF_V + 64 * LVV)        // 8960
#define AOFF_MD (AOFF_P + 8 * 16 * LPP)    // 17664
#define ATT_SMEM ((AOFF_MD + 64) * 4)      // 70912 bytes

__global__ __launch_bounds__(256)
void attn_mma(const float* __restrict__ mask)
{
    extern __shared__ uint32_t sm[];
    uint32_t* Ks = sm;
    uint32_t* Vs = sm + AOFF_V;
    float*    madd = reinterpret_cast<float*>(sm + AOFF_MD);

    const int bh = blockIdx.y;
    const int b_ = bh >> 4;
    const int h  = bh & (NH - 1);
    const int q0 = blockIdx.x * 128;
    const int tid = threadIdx.x;
    const int wid = tid >> 5;
    const int lane = tid & 31;
    const int r4 = lane >> 2;
    const int c4 = lane & 3;
    uint32_t* Pw = sm + AOFF_P + wid * 16 * LPP;

    const int qrow = q0 + wid * 16;   // warp's first query row (within S)

    // Q fragments in registers for entire KV loop
    uint32_t aq[8][4];
    {
        const float* Qb = g_Q + ((size_t)bh * SS + qrow) * HD;
#pragma unroll
        for (int ks = 0; ks < 8; ks++) {
            aq[ks][0] = cvt_tf32(Qb[(size_t)r4 * HD + ks * 8 + c4]);
            aq[ks][1] = cvt_tf32(Qb[(size_t)(r4 + 8) * HD + ks * 8 + c4]);
            aq[ks][2] = cvt_tf32(Qb[(size_t)r4 * HD + ks * 8 + c4 + 4]);
            aq[ks][3] = cvt_tf32(Qb[(size_t)(r4 + 8) * HD + ks * 8 + c4 + 4]);
        }
    }

    float ctx[8][4];
#pragma unroll
    for (int nt = 0; nt < 8; nt++)
#pragma unroll
        for (int i = 0; i < 4; i++) ctx[nt][i] = 0.f;
    float m0 = -1e30f, m1 = -1e30f, l0 = 0.f, l1 = 0.f;
    const float scale = 0.125f;

    const int krow = tid >> 2;
    const int kcb = (tid & 3) * 16;

    for (int kt = 0; kt < SS; kt += 64) {
        __syncthreads();
        // stage K [key][d] and V [key][d], tf32
        {
            const float* Kp = g_K + ((size_t)bh * SS + kt + krow) * HD + kcb;
            const float* Vp = g_V + ((size_t)bh * SS + kt + krow) * HD + kcb;
#pragma unroll
            for (int i = 0; i < 4; i++) {
                float4 v = *reinterpret_cast<const float4*>(&Kp[i * 4]);
                uint32_t* p = &Ks[krow * LKK + kcb + i * 4];
                p[0] = cvt_tf32(v.x); p[1] = cvt_tf32(v.y); p[2] = cvt_tf32(v.z); p[3] = cvt_tf32(v.w);
            }
#pragma unroll
            for (int i = 0; i < 4; i++) {
                float4 v = *reinterpret_cast<const float4*>(&Vp[i * 4]);
                uint32_t* p = &Vs[krow * LVV + kcb + i * 4];
                p[0] = cvt_tf32(v.x); p[1] = cvt_tf32(v.y); p[2] = cvt_tf32(v.z); p[3] = cvt_tf32(v.w);
            }
            if (tid < 64)
                madd[tid] = (1.0f - mask[b_ * SS + kt + tid]) * -10000.0f;
        }
        __syncthreads();

        // ---- S = Q @ K^T ----
        float sf[8][4];
#pragma unroll
        for (int nt = 0; nt < 8; nt++) {
            sf[nt][0] = sf[nt][1] = sf[nt][2] = sf[nt][3] = 0.f;
#pragma unroll
            for (int ks = 0; ks < 8; ks++) {
                const uint32_t* base = &Ks[(nt * 8 + r4) * LKK + ks * 8 + c4];
                mma_tf32(sf[nt][0], sf[nt][1], sf[nt][2], sf[nt][3],
                         aq[ks][0], aq[ks][1], aq[ks][2], aq[ks][3],
                         base[0], base[4]);
            }
        }

        // ---- scale + mask + online softmax ----
        float rm0 = -1e30f, rm1 = -1e30f;
#pragma unroll
        for (int nt = 0; nt < 8; nt++) {
            float ma = madd[nt * 8 + 2 * c4];
            float mb = madd[nt * 8 + 2 * c4 + 1];
            sf[nt][0] = sf[nt][0] * scale + ma;
            sf[nt][1] = sf[nt][1] * scale + mb;
            sf[nt][2] = sf[nt][2] * scale + ma;
            sf[nt][3] = sf[nt][3] * scale + mb;
            rm0 = fmaxf(rm0, fmaxf(sf[nt][0], sf[nt][1]));
            rm1 = fmaxf(rm1, fmaxf(sf[nt][2], sf[nt][3]));
        }
        rm0 = fmaxf(rm0, __shfl_xor_sync(0xffffffff, rm0, 1));
        rm0 = fmaxf(rm0, __shfl_xor_sync(0xffffffff, rm0, 2));
        rm1 = fmaxf(rm1, __shfl_xor_sync(0xffffffff, rm1, 1));
        rm1 = fmaxf(rm1, __shfl_xor_sync(0xffffffff, rm1, 2));

        float nm0 = fmaxf(m0, rm0), nm1 = fmaxf(m1, rm1);
        float corr0 = __expf(m0 - nm0), corr1 = __expf(m1 - nm1);
        m0 = nm0; m1 = nm1;

        float rs0 = 0.f, rs1 = 0.f;
#pragma unroll
        for (int nt = 0; nt < 8; nt++) {
            sf[nt][0] = __expf(sf[nt][0] - nm0);
            sf[nt][1] = __expf(sf[nt][1] - nm0);
            sf[nt][2] = __expf(sf[nt][2] - nm1);
            sf[nt][3] = __expf(sf[nt][3] - nm1);
            rs0 += sf[nt][0] + sf[nt][1];
            rs1 += sf[nt][2] + sf[nt][3];
        }
        rs0 += __shfl_xor_sync(0xffffffff, rs0, 1);
        rs0 += __shfl_xor_sync(0xffffffff, rs0, 2);
        rs1 += __shfl_xor_sync(0xffffffff, rs1, 1);
        rs1 += __shfl_xor_sync(0xffffffff, rs1, 2);
        l0 = l0 * corr0 + rs0;
        l1 = l1 * corr1 + rs1;

#pragma unroll
        for (int nt = 0; nt < 8; nt++) {
            ctx[nt][0] *= corr0; ctx[nt][1] *= corr0;
            ctx[nt][2] *= corr1; ctx[nt][3] *= corr1;
        }

        // ---- store P (tf32) to warp-private SMEM ----
#pragma unroll
        for (int nt = 0; nt < 8; nt++) {
            uint2 lo = make_uint2(cvt_tf32(sf[nt][0]), cvt_tf32(sf[nt][1]));
            uint2 hi = make_uint2(cvt_tf32(sf[nt][2]), cvt_tf32(sf[nt][3]));
            *reinterpret_cast<uint2*>(&Pw[r4 * LPP + nt * 8 + 2 * c4]) = lo;
            *reinterpret_cast<uint2*>(&Pw[(r4 + 8) * LPP + nt * 8 + 2 * c4]) = hi;
        }
        __syncwarp();

        // ---- ctx += P @ V ----
#pragma unroll
        for (int ks2 = 0; ks2 < 8; ks2++) {
            uint32_t ap0 = Pw[r4 * LPP + ks2 * 8 + c4];
            uint32_t ap1 = Pw[(r4 + 8) * LPP + ks2 * 8 + c4];
            uint32_t ap2 = Pw[r4 * LPP + ks2 * 8 + c4 + 4];
            uint32_t ap3 = Pw[(r4 + 8) * LPP + ks2 * 8 + c4 + 4];
#pragma unroll
            for (int nt2 = 0; nt2 < 8; nt2++) {
                uint32_t b0 = Vs[(ks2 * 8 + c4) * LVV + nt2 * 8 + r4];
                uint32_t b1 = Vs[(ks2 * 8 + c4 + 4) * LVV + nt2 * 8 + r4];
                mma_tf32(ctx[nt2][0], ctx[nt2][1], ctx[nt2][2], ctx[nt2][3],
                         ap0, ap1, ap2, ap3, b0, b1);
            }
        }
        __syncwarp();
    }

    // ---- epilogue: normalize, write to g_ctx [B,S,E] ----
    float inv0 = 1.0f / l0;
    float inv1 = 1.0f / l1;
    const int sq0 = qrow + r4;
    float* C0 = g_ctx + ((size_t)(b_ * SS + sq0) * EDIM) + h * HD;
    float* C1 = g_ctx + ((size_t)(b_ * SS + sq0 + 8) * EDIM) + h * HD;
#pragma unroll
    for (int nt2 = 0; nt2 < 8; nt2++) {
        const int col = nt2 * 8 + 2 * c4;
        *reinterpret_cast<float2*>(&C0[col]) = make_float2(ctx[nt2][0] * inv0, ctx[nt2][1] * inv0);
        *reinterpret_cast<float2*>(&C1[col]) = make_float2(ctx[nt2][2] * inv1, ctx[nt2][3] * inv1);
    }
}

// ============================ launch ============================
extern "C" void kernel_launch(void* const* d_in, const int* in_sizes, int n_in,
                              void* d_out, int out_size)
{
    const float* X    = (const float*)d_in[0];
    const float* mask = (const float*)d_in[1];
    const float* Wq   = (const float*)d_in[2];
    const float* bq   = (const float*)d_in[3];
    const float* Wk   = (const float*)d_in[4];
    const float* bk   = (const float*)d_in[5];
    const float* Wv   = (const float*)d_in[6];
    const float* bv   = (const float*)d_in[7];
    const float* Wo   = (const float*)d_in[8];
    const float* bo   = (const float*)d_in[9];
    float* out = (float*)d_out;

    const int gemm_smem = 4 * TILE_U32 * 4;   // 73728
    cudaFuncSetAttribute(gemm_qkv, cudaFuncAttributeMaxDynamicSharedMemorySize, gemm_smem);
    cudaFuncSetAttribute(gemm_out, cudaFuncAttributeMaxDynamicSharedMemorySize, gemm_smem);
    cudaFuncSetAttribute(attn_mma, cudaFuncAttributeMaxDynamicSharedMemorySize, ATT_SMEM);

    dim3 tgrid(32, 32, 4), tblk(32, 8);
    transpose4<<<tgrid, tblk>>>(Wq, Wk, Wv, Wo);

    dim3 qkvgrid(MTOT / GBM, EDIM / GBN, 3);   // 32 x 8 x 3
    gemm_qkv<<<qkvgrid, 256, gemm_smem>>>(X, bq, bk, bv);

    dim3 agrid(SS / 128, BB * NH);             // 16 x 32
    attn_mma<<<agrid, 256, ATT_SMEM>>>(mask);

    dim3 ogrid(MTOT / GBM, EDIM / GBN);        // 32 x 8
    gemm_out<<<ogrid, 256, gemm_smem>>>(bo, out);
}

// round 7
// speedup vs baseline: 3.4570x; 1.0004x over previous
#include <cuda_runtime.h>
#include <math.h>
#include <cstdint>

#define EDIM 1024
#define NH   16
#define HD   64
#define BB   2
#define SS   2048
#define MTOT (BB*SS)   // 4096

// Scratch
__device__ float g_Q[MTOT*EDIM];
__device__ float g_K[MTOT*EDIM];
__device__ float g_V[MTOT*EDIM];
__device__ float g_ctx[MTOT*EDIM];
__device__ float g_Wt[4][EDIM*EDIM];   // transposed weights [n][k]

__device__ __forceinline__ uint32_t cvt_tf32(float x) {
    uint32_t r; asm("cvt.rna.tf32.f32 %0, %1;" : "=r"(r) : "f"(x));
    return r;
}

__device__ __forceinline__ void mma_tf32(float& d0, float& d1, float& d2, float& d3,
                                         uint32_t a0, uint32_t a1, uint32_t a2, uint32_t a3,
                                         uint32_t b0, uint32_t b1) {
    asm volatile(
        "mma.sync.aligned.m16n8k8.row.col.f32.tf32.tf32.f32 "
        "{%0,%1,%2,%3},{%4,%5,%6,%7},{%8,%9},{%0,%1,%2,%3};"
        : "+f"(d0), "+f"(d1), "+f"(d2), "+f"(d3)
        : "r"(a0), "r"(a1), "r"(a2), "r"(a3), "r"(b0), "r"(b1));
}

// ============================ fused transpose (grid.z selects W) ============================
__global__ __launch_bounds__(256)
void transpose4(const float* __restrict__ w0, const float* __restrict__ w1,
                const float* __restrict__ w2, const float* __restrict__ w3)
{
    const float* in = (blockIdx.z == 0) ? w0 : (blockIdx.z == 1) ? w1 : (blockIdx.z == 2) ? w2 : w3;
    float* out = g_Wt[blockIdx.z];
    __shared__ float t[32][33];
    int x = blockIdx.x * 32 + threadIdx.x;
    int y = blockIdx.y * 32 + threadIdx.y;
#pragma unroll
    for (int j = 0; j < 32; j += 8)
        t[threadIdx.y + j][threadIdx.x] = in[(size_t)(y + j) * EDIM + x];
    __syncthreads();
    x = blockIdx.y * 32 + threadIdx.x;
    y = blockIdx.x * 32 + threadIdx.y;
#pragma unroll
    for (int j = 0; j < 32; j += 8)
        out[(size_t)(y + j) * EDIM + x] = t[threadIdx.x][threadIdx.y + j];
}

// ============================ tf32 mma.sync GEMM ============================
#define GBM 128
#define GBN 128
#define GBK 32
#define LDP 36
#define TILE_U32 (128 * LDP)

struct GemmSmem { uint32_t a[2][TILE_U32]; uint32_t b[2][TILE_U32]; };

__device__ __forceinline__ void gemm_body(const float* __restrict__ A, const float* __restrict__ Wt,
                                          const float* __restrict__ bias, float* __restrict__ C,
                                          int head_layout, uint32_t* sm, int m0, int n0)
{
    uint32_t* As[2] = { sm,                sm + 2 * TILE_U32 };
    uint32_t* Bs[2] = { sm + TILE_U32,     sm + 3 * TILE_U32 };

    const int tid = threadIdx.x;
    const int wid = tid >> 5;
    const int lane = tid & 31;
    const int warp_m = (wid & 3) * 32;
    const int warp_n = (wid >> 2) * 64;
    const int r4 = lane >> 2;
    const int c4 = lane & 3;

    float acc[2][8][4];
#pragma unroll
    for (int mt = 0; mt < 2; mt++)
#pragma unroll
        for (int nt = 0; nt < 8; nt++)
#pragma unroll
            for (int i = 0; i < 4; i++) acc[mt][nt][i] = 0.f;

    const int sr = tid >> 1;
    const int sc = (tid & 1) * 16;
    auto stage = [&](int buf, int k0) {
        uint32_t* Ad = As[buf];
        uint32_t* Bd = Bs[buf];
#pragma unroll
        for (int i = 0; i < 4; i++) {
            float4 v = *reinterpret_cast<const float4*>(&A[(size_t)(m0 + sr) * EDIM + k0 + sc + i * 4]);
            uint32_t* p = &Ad[sr * LDP + sc + i * 4];
            p[0] = cvt_tf32(v.x); p[1] = cvt_tf32(v.y); p[2] = cvt_tf32(v.z); p[3] = cvt_tf32(v.w);
        }
#pragma unroll
        for (int i = 0; i < 4; i++) {
            float4 v = *reinterpret_cast<const float4*>(&Wt[(size_t)(n0 + sr) * EDIM + k0 + sc + i * 4]);
            uint32_t* p = &Bd[sr * LDP + sc + i * 4];
            p[0] = cvt_tf32(v.x); p[1] = cvt_tf32(v.y); p[2] = cvt_tf32(v.z); p[3] = cvt_tf32(v.w);
        }
    };

    stage(0, 0);
    __syncthreads();

    const int NCHUNK = EDIM / GBK;
    for (int c = 0; c < NCHUNK; c++) {
        const int cur = c & 1;
        if (c + 1 < NCHUNK) stage(cur ^ 1, (c + 1) * GBK);

        const uint32_t* Ab = As[cur];
        const uint32_t* Bb = Bs[cur];
#pragma unroll
        for (int ks = 0; ks < 4; ks++) {
            const int kb = ks * 8;
            uint32_t af[2][4];
#pragma unroll
            for (int mt = 0; mt < 2; mt++) {
                const uint32_t* base = &Ab[(warp_m + mt * 16 + r4) * LDP + kb + c4];
                af[mt][0] = base[0];
                af[mt][1] = base[8 * LDP];
                af[mt][2] = base[4];
                af[mt][3] = base[8 * LDP + 4];
            }
            uint32_t bf[8][2];
#pragma unroll
            for (int nt = 0; nt < 8; nt++) {
                const uint32_t* base = &Bb[(warp_n + nt * 8 + r4) * LDP + kb + c4];
                bf[nt][0] = base[0];
                bf[nt][1] = base[4];
            }
#pragma unroll
            for (int mt = 0; mt < 2; mt++)
#pragma unroll
                for (int nt = 0; nt < 8; nt++)
                    mma_tf32(acc[mt][nt][0], acc[mt][nt][1], acc[mt][nt][2], acc[mt][nt][3],
                             af[mt][0], af[mt][1], af[mt][2], af[mt][3],
                             bf[nt][0], bf[nt][1]);
        }
        __syncthreads();
    }

#pragma unroll
    for (int mt = 0; mt < 2; mt++) {
#pragma unroll
        for (int half = 0; half < 2; half++) {
            const int m = m0 + warp_m + mt * 16 + r4 + half * 8;
            const int b_ = m >> 11;
            const int s_ = m & (SS - 1);
#pragma unroll
            for (int nt = 0; nt < 8; nt++) {
                const int col = n0 + warp_n + nt * 8 + 2 * c4;
                float2 o;
                o.x = acc[mt][nt][half * 2 + 0] + bias[col];
                o.y = acc[mt][nt][half * 2 + 1] + bias[col + 1];
                if (head_layout) {
                    const int h = col >> 6;
                    const int d = col & (HD - 1);
                    *reinterpret_cast<float2*>(
                        &C[(((size_t)(b_ * NH + h) * SS + s_) * HD) + d]) = o;
                } else {
                    *reinterpret_cast<float2*>(&C[(size_t)m * EDIM + col]) = o;
                }
            }
        }
    }
}

// fused QKV projection: grid.z in {0,1,2} picks weight/bias/output
__global__ __launch_bounds__(256)
void gemm_qkv(const float* __restrict__ X,
              const float* __restrict__ bq, const float* __restrict__ bk,
              const float* __restrict__ bv)
{
    extern __shared__ uint32_t sm[];
    const int z = blockIdx.z;
    const float* Wt = g_Wt[z];
    const float* bias = (z == 0) ? bq : (z == 1) ? bk : bv;
    float* C = (z == 0) ? g_Q : (z == 1) ? g_K : g_V;
    gemm_body(X, Wt, bias, C, 1, sm, blockIdx.x * GBM, blockIdx.y * GBN);
}

__global__ __launch_bounds__(256)
void gemm_out(const float* __restrict__ bo, float* __restrict__ C)
{
    extern __shared__ uint32_t sm[];
    gemm_body(g_ctx, g_Wt[3], bo, C, 0, sm, blockIdx.x * GBM, blockIdx.y * GBN);
}

// ============================ flash attention with mma.sync tf32 ============================
// CTA: 128 q rows of one (b,h); 8 warps x 16 rows. KV tiles of 64.
#define LKK 68
#define LVV 72
#define LPP 68
#define AOFF_V  (64 * LKK)                 // 4352
#define AOFF_P  (AOFF_V + 64 * LVV)        // 8960
#define AOFF_MD (AOFF_P + 8 * 16 * LPP)    // 17664
#define ATT_SMEM ((AOFF_MD + 64) * 4)      // 70912 bytes

__global__ __launch_bounds__(256)
void attn_mma(const float* __restrict__ mask)
{
    extern __shared__ uint32_t sm[];
    uint32_t* Ks = sm;
    uint32_t* Vs = sm + AOFF_V;
    float*    madd = reinterpret_cast<float*>(sm + AOFF_MD);

    const int bh = blockIdx.y;
    const int b_ = bh >> 4;
    const int h  = bh & (NH - 1);
    const int q0 = blockIdx.x * 128;
    const int tid = threadIdx.x;
    const int wid = tid >> 5;
    const int lane = tid & 31;
    const int r4 = lane >> 2;
    const int c4 = lane & 3;
    uint32_t* Pw = sm + AOFF_P + wid * 16 * LPP;

    const int qrow = q0 + wid * 16;   // warp's first query row (within S)

    // Q fragments in registers for entire KV loop
    uint32_t aq[8][4];
    {
        const float* Qb = g_Q + ((size_t)bh * SS + qrow) * HD;
#pragma unroll
        for (int ks = 0; ks < 8; ks++) {
            aq[ks][0] = cvt_tf32(Qb[(size_t)r4 * HD + ks * 8 + c4]);
            aq[ks][1] = cvt_tf32(Qb[(size_t)(r4 + 8) * HD + ks * 8 + c4]);
            aq[ks][2] = cvt_tf32(Qb[(size_t)r4 * HD + ks * 8 + c4 + 4]);
            aq[ks][3] = cvt_tf32(Qb[(size_t)(r4 + 8) * HD + ks * 8 + c4 + 4]);
        }
    }

    float ctx[8][4];
#pragma unroll
    for (int nt = 0; nt < 8; nt++)
#pragma unroll
        for (int i = 0; i < 4; i++) ctx[nt][i] = 0.f;
    float m0 = -1e30f, m1 = -1e30f, l0 = 0.f, l1 = 0.f;
    const float scale = 0.125f;

    const int krow = tid >> 2;
    const int kcb = (tid & 3) * 16;

    for (int kt = 0; kt < SS; kt += 64) {
        __syncthreads();
        // stage K [key][d] and V [key][d], tf32
        {
            const float* Kp = g_K + ((size_t)bh * SS + kt + krow) * HD + kcb;
            const float* Vp = g_V + ((size_t)bh * SS + kt + krow) * HD + kcb;
#pragma unroll
            for (int i = 0; i < 4; i++) {
                float4 v = *reinterpret_cast<const float4*>(&Kp[i * 4]);
                uint32_t* p = &Ks[krow * LKK + kcb + i * 4];
                p[0] = cvt_tf32(v.x); p[1] = cvt_tf32(v.y); p[2] = cvt_tf32(v.z); p[3] = cvt_tf32(v.w);
            }
#pragma unroll
            for (int i = 0; i < 4; i++) {
                float4 v = *reinterpret_cast<const float4*>(&Vp[i * 4]);
                uint32_t* p = &Vs[krow * LVV + kcb + i * 4];
                p[0] = cvt_tf32(v.x); p[1] = cvt_tf32(v.y); p[2] = cvt_tf32(v.z); p[3] = cvt_tf32(v.w);
            }
            if (tid < 64)
                madd[tid] = (1.0f - mask[b_ * SS + kt + tid]) * -10000.0f;
        }
        __syncthreads();

        // ---- S = Q @ K^T ----
        float sf[8][4];
#pragma unroll
        for (int nt = 0; nt < 8; nt++) {
            sf[nt][0] = sf[nt][1] = sf[nt][2] = sf[nt][3] = 0.f;
#pragma unroll
            for (int ks = 0; ks < 8; ks++) {
                const uint32_t* base = &Ks[(nt * 8 + r4) * LKK + ks * 8 + c4];
                mma_tf32(sf[nt][0], sf[nt][1], sf[nt][2], sf[nt][3],
                         aq[ks][0], aq[ks][1], aq[ks][2], aq[ks][3],
                         base[0], base[4]);
            }
        }

        // ---- scale + mask + online softmax ----
        float rm0 = -1e30f, rm1 = -1e30f;
#pragma unroll
        for (int nt = 0; nt < 8; nt++) {
            float ma = madd[nt * 8 + 2 * c4];
            float mb = madd[nt * 8 + 2 * c4 + 1];
            sf[nt][0] = sf[nt][0] * scale + ma;
            sf[nt][1] = sf[nt][1] * scale + mb;
            sf[nt][2] = sf[nt][2] * scale + ma;
            sf[nt][3] = sf[nt][3] * scale + mb;
            rm0 = fmaxf(rm0, fmaxf(sf[nt][0], sf[nt][1]));
            rm1 = fmaxf(rm1, fmaxf(sf[nt][2], sf[nt][3]));
        }
        rm0 = fmaxf(rm0, __shfl_xor_sync(0xffffffff, rm0, 1));
        rm0 = fmaxf(rm0, __shfl_xor_sync(0xffffffff, rm0, 2));
        rm1 = fmaxf(rm1, __shfl_xor_sync(0xffffffff, rm1, 1));
        rm1 = fmaxf(rm1, __shfl_xor_sync(0xffffffff, rm1, 2));

        float nm0 = fmaxf(m0, rm0), nm1 = fmaxf(m1, rm1);
        float corr0 = __expf(m0 - nm0), corr1 = __expf(m1 - nm1);
        m0 = nm0; m1 = nm1;

        float rs0 = 0.f, rs1 = 0.f;
#pragma unroll
        for (int nt = 0; nt < 8; nt++) {
            sf[nt][0] = __expf(sf[nt][0] - nm0);
            sf[nt][1] = __expf(sf[nt][1] - nm0);
            sf[nt][2] = __expf(sf[nt][2] - nm1);
            sf[nt][3] = __expf(sf[nt][3] - nm1);
            rs0 += sf[nt][0] + sf[nt][1];
            rs1 += sf[nt][2] + sf[nt][3];
        }
        rs0 += __shfl_xor_sync(0xffffffff, rs0, 1);
        rs0 += __shfl_xor_sync(0xffffffff, rs0, 2);
        rs1 += __shfl_xor_sync(0xffffffff, rs1, 1);
        rs1 += __shfl_xor_sync(0xffffffff, rs1, 2);
        l0 = l0 * corr0 + rs0;
        l1 = l1 * corr1 + rs1;

#pragma unroll
        for (int nt = 0; nt < 8; nt++) {
            ctx[nt][0] *= corr0; ctx[nt][1] *= corr0;
            ctx[nt][2] *= corr1; ctx[nt][3] *= corr1;
        }

        // ---- store P (tf32) to warp-private SMEM ----
#pragma unroll
        for (int nt = 0; nt < 8; nt++) {
            uint2 lo = make_uint2(cvt_tf32(sf[nt][0]), cvt_tf32(sf[nt][1]));
            uint2 hi = make_uint2(cvt_tf32(sf[nt][2]), cvt_tf32(sf[nt][3]));
            *reinterpret_cast<uint2*>(&Pw[r4 * LPP + nt * 8 + 2 * c4]) = lo;
            *reinterpret_cast<uint2*>(&Pw[(r4 + 8) * LPP + nt * 8 + 2 * c4]) = hi;
        }
        __syncwarp();

        // ---- ctx += P @ V ----
#pragma unroll
        for (int ks2 = 0; ks2 < 8; ks2++) {
            uint32_t ap0 = Pw[r4 * LPP + ks2 * 8 + c4];
            uint32_t ap1 = Pw[(r4 + 8) * LPP + ks2 * 8 + c4];
            uint32_t ap2 = Pw[r4 * LPP + ks2 * 8 + c4 + 4];
            uint32_t ap3 = Pw[(r4 + 8) * LPP + ks2 * 8 + c4 + 4];
#pragma unroll
            for (int nt2 = 0; nt2 < 8; nt2++) {
                uint32_t b0 = Vs[(ks2 * 8 + c4) * LVV + nt2 * 8 + r4];
                uint32_t b1 = Vs[(ks2 * 8 + c4 + 4) * LVV + nt2 * 8 + r4];
                mma_tf32(ctx[nt2][0], ctx[nt2][1], ctx[nt2][2], ctx[nt2][3],
                         ap0, ap1, ap2, ap3, b0, b1);
            }
        }
        __syncwarp();
    }

    // ---- epilogue: normalize, write to g_ctx [B,S,E] ----
    float inv0 = 1.0f / l0;
    float inv1 = 1.0f / l1;
    const int sq0 = qrow + r4;
    float* C0 = g_ctx + ((size_t)(b_ * SS + sq0) * EDIM) + h * HD;
    float* C1 = g_ctx + ((size_t)(b_ * SS + sq0 + 8) * EDIM) + h * HD;
#pragma unroll
    for (int nt2 = 0; nt2 < 8; nt2++) {
        const int col = nt2 * 8 + 2 * c4;
        *reinterpret_cast<float2*>(&C0[col]) = make_float2(ctx[nt2][0] * inv0, ctx[nt2][1] * inv0);
        *reinterpret_cast<float2*>(&C1[col]) = make_float2(ctx[nt2][2] * inv1, ctx[nt2][3] * inv1);
    }
}

// ============================ launch ============================
extern "C" void kernel_launch(void* const* d_in, const int* in_sizes, int n_in,
                              void* d_out, int out_size)
{
    const float* X    = (const float*)d_in[0];
    const float* mask = (const float*)d_in[1];
    const float* Wq   = (const float*)d_in[2];
    const float* bq   = (const float*)d_in[3];
    const float* Wk   = (const float*)d_in[4];
    const float* bk   = (const float*)d_in[5];
    const float* Wv   = (const float*)d_in[6];
    const float* bv   = (const float*)d_in[7];
    const float* Wo   = (const float*)d_in[8];
    const float* bo   = (const float*)d_in[9];
    float* out = (float*)d_out;

    const int gemm_smem = 4 * TILE_U32 * 4;   // 73728
    cudaFuncSetAttribute(gemm_qkv, cudaFuncAttributeMaxDynamicSharedMemorySize, gemm_smem);
    cudaFuncSetAttribute(gemm_out, cudaFuncAttributeMaxDynamicSharedMemorySize, gemm_smem);
    cudaFuncSetAttribute(attn_mma, cudaFuncAttributeMaxDynamicSharedMemorySize, ATT_SMEM);

    dim3 tgrid(32, 32, 4), tblk(32, 8);
    transpose4<<<tgrid, tblk>>>(Wq, Wk, Wv, Wo);

    dim3 qkvgrid(MTOT / GBM, EDIM / GBN, 3);   // 32 x 8 x 3
    gemm_qkv<<<qkvgrid, 256, gemm_smem>>>(X, bq, bk, bv);

    dim3 agrid(SS / 128, BB * NH);             // 16 x 32
    attn_mma<<<agrid, 256, ATT_SMEM>>>(mask);

    dim3 ogrid(MTOT / GBM, EDIM / GBN);        // 32 x 8
    gemm_out<<<ogrid, 256, gemm_smem>>>(bo, out);
}